// round 4
// baseline (speedup 1.0000x reference)
#include <cuda_runtime.h>

// Problem constants
#define T_ 1024
#define B_ 4
#define E_ 512
#define H_ 8
#define HD_ 64
#define E3_ 1536

// Scratch (static device globals — allocation-free contract)
__device__ float g_qkv[T_ * B_ * E3_];   // [t,b, 3E]  (q | k | v)
__device__ float g_ctx[T_ * B_ * E_];    // [t,b, E]

// ---------------------------------------------------------------------------
// GEMM: C[m,n] = bias[n] + sum_k A[m,k] * W[n,k]
// A: [M,K] row-major (lda=K), W: [N,K] row-major, C: row-major (ldc).
// 64x64 tile, BK=32, 256 threads, 4x4 micro-tile, transposed smem tiles
// (conflict-free LDS.128 in the inner loop).
// ---------------------------------------------------------------------------
__global__ __launch_bounds__(256)
void gemm_nt_bias(const float* __restrict__ A, const float* __restrict__ W,
                  const float* __restrict__ bias, float* __restrict__ C,
                  int K, int ldc)
{
    constexpr int BK = 32;
    __shared__ float As[BK][64];   // As[k][m]
    __shared__ float Ws[BK][64];   // Ws[k][n]
    const int m0 = blockIdx.x * 64;
    const int n0 = blockIdx.y * 64;
    const int tid = threadIdx.x;
    const int my = tid >> 4;       // 0..15 (m block)
    const int nx = tid & 15;       // 0..15 (n block)

    float acc[4][4];
#pragma unroll
    for (int i = 0; i < 4; i++)
#pragma unroll
        for (int j = 0; j < 4; j++) acc[i][j] = 0.f;

    for (int kk = 0; kk < K; kk += BK) {
        __syncthreads();
#pragma unroll
        for (int p = 0; p < 2; p++) {
            int idx = p * 256 + tid;
            int r  = idx & 63;       // row within tile (lane-contiguous -> CF stores)
            int k4 = idx >> 6;       // 0..7
            float4 av = *(const float4*)&A[(size_t)(m0 + r) * K + kk + 4 * k4];
            As[4*k4+0][r] = av.x; As[4*k4+1][r] = av.y;
            As[4*k4+2][r] = av.z; As[4*k4+3][r] = av.w;
            float4 wv = *(const float4*)&W[(size_t)(n0 + r) * K + kk + 4 * k4];
            Ws[4*k4+0][r] = wv.x; Ws[4*k4+1][r] = wv.y;
            Ws[4*k4+2][r] = wv.z; Ws[4*k4+3][r] = wv.w;
        }
        __syncthreads();
#pragma unroll 8
        for (int k = 0; k < BK; k++) {
            float4 a4 = *(const float4*)&As[k][4 * my];
            float4 w4 = *(const float4*)&Ws[k][4 * nx];
            float aa[4] = {a4.x, a4.y, a4.z, a4.w};
            float ww[4] = {w4.x, w4.y, w4.z, w4.w};
#pragma unroll
            for (int i = 0; i < 4; i++)
#pragma unroll
                for (int j = 0; j < 4; j++) acc[i][j] += aa[i] * ww[j];
        }
    }
#pragma unroll
    for (int i = 0; i < 4; i++) {
        float4 o;
        o.x = acc[i][0] + bias[n0 + 4*nx + 0];
        o.y = acc[i][1] + bias[n0 + 4*nx + 1];
        o.z = acc[i][2] + bias[n0 + 4*nx + 2];
        o.w = acc[i][3] + bias[n0 + 4*nx + 3];
        *(float4*)&C[(size_t)(m0 + 4*my + i) * ldc + n0 + 4*nx] = o;
    }
}

// ---------------------------------------------------------------------------
// Fused attention: per (head bh, 64-query tile). Streams K/V/bias over s in
// 64-wide tiles with online softmax. dist[b,t,s,h] read once (L2 shares the
// stride-8 sectors across the 8 heads, which are adjacent in gridDim.y).
// Thread layout: 256 threads = (my 0..15) x (sx 0..15), 4x4 micro-tiles.
// ---------------------------------------------------------------------------
__global__ __launch_bounds__(256)
void attn_kernel(const float* __restrict__ dist)
{
    extern __shared__ float sm[];
    float* Qs = sm;                 // [64][64]  Qs[d][r]  (transposed, scaled)
    float* Ks = sm + 64 * 64;       // [64][64]  Ks[d][c]  (transposed)
    float* Vs = sm + 2 * 64 * 64;   // [64][68]  Vs[s][d]
    float* Ps = Vs + 64 * 68;       // [64][68]  Ps[r][c]

    const int qt = blockIdx.x;           // 0..15
    const int bh = blockIdx.y;           // 0..31  (b*8 + h): heads adjacent
    const int b = bh >> 3, h = bh & 7;
    const int t0 = qt * 64;
    const int tid = threadIdx.x;
    const int my = tid >> 4, sx = tid & 15;
    const float scale = 0.125f;          // 1/sqrt(64)

    // Load Q tile (transposed + scaled). Lane-contiguous r -> CF smem stores.
#pragma unroll
    for (int p = 0; p < 4; p++) {
        int idx = p * 256 + tid;
        int r = idx & 63, d4 = idx >> 6;
        float4 v = *(const float4*)&g_qkv[((size_t)(t0 + r) * B_ + b) * E3_ + h * HD_ + 4 * d4];
        Qs[(4*d4+0)*64 + r] = v.x * scale; Qs[(4*d4+1)*64 + r] = v.y * scale;
        Qs[(4*d4+2)*64 + r] = v.z * scale; Qs[(4*d4+3)*64 + r] = v.w * scale;
    }

    float m_run[4] = {-1e30f, -1e30f, -1e30f, -1e30f};
    float l_run[4] = {0.f, 0.f, 0.f, 0.f};
    float O[4][4];
#pragma unroll
    for (int i = 0; i < 4; i++)
#pragma unroll
        for (int j = 0; j < 4; j++) O[i][j] = 0.f;

    for (int st = 0; st < 16; st++) {
        const int s0 = st * 64;
        __syncthreads();   // prior AV done with Vs/Ps
        // K tile (transposed)
#pragma unroll
        for (int p = 0; p < 4; p++) {
            int idx = p * 256 + tid;
            int r = idx & 63, d4 = idx >> 6;
            float4 kv = *(const float4*)&g_qkv[((size_t)(s0 + r) * B_ + b) * E3_ + E_ + h * HD_ + 4 * d4];
            Ks[(4*d4+0)*64 + r] = kv.x; Ks[(4*d4+1)*64 + r] = kv.y;
            Ks[(4*d4+2)*64 + r] = kv.z; Ks[(4*d4+3)*64 + r] = kv.w;
        }
        // V tile (natural layout, padded stride 68, float4 CF stores)
#pragma unroll
        for (int p = 0; p < 4; p++) {
            int idx = p * 256 + tid;
            int d4 = idx & 15, s = idx >> 4;
            float4 vv = *(const float4*)&g_qkv[((size_t)(s0 + s) * B_ + b) * E3_ + 2 * E_ + h * HD_ + 4 * d4];
            *(float4*)&Vs[s * 68 + 4 * d4] = vv;
        }
        __syncthreads();

        // S = Q K^T (4x4 per thread)
        float S[4][4];
#pragma unroll
        for (int i = 0; i < 4; i++)
#pragma unroll
            for (int j = 0; j < 4; j++) S[i][j] = 0.f;
#pragma unroll 8
        for (int d = 0; d < 64; d++) {
            float4 q4 = *(const float4*)&Qs[d * 64 + 4 * my];
            float4 k4 = *(const float4*)&Ks[d * 64 + 4 * sx];
            float qa[4] = {q4.x, q4.y, q4.z, q4.w};
            float ka[4] = {k4.x, k4.y, k4.z, k4.w};
#pragma unroll
            for (int i = 0; i < 4; i++)
#pragma unroll
                for (int j = 0; j < 4; j++) S[i][j] += qa[i] * ka[j];
        }
        // + bias  dist[b, t0+r, s0+c, h]
        {
            const size_t base = (((size_t)b * T_ + (t0 + 4 * my)) * T_ + (s0 + 4 * sx)) * H_ + h;
#pragma unroll
            for (int i = 0; i < 4; i++)
#pragma unroll
                for (int j = 0; j < 4; j++)
                    S[i][j] += __ldg(&dist[base + ((size_t)i * T_ + j) * H_]);
        }
        // online softmax (rows split across 16 consecutive lanes)
#pragma unroll
        for (int i = 0; i < 4; i++) {
            float mx = fmaxf(fmaxf(S[i][0], S[i][1]), fmaxf(S[i][2], S[i][3]));
#pragma unroll
            for (int off = 8; off > 0; off >>= 1)
                mx = fmaxf(mx, __shfl_xor_sync(0xffffffffu, mx, off));
            float mnew = fmaxf(m_run[i], mx);
            float corr = __expf(m_run[i] - mnew);
            float rs = 0.f;
#pragma unroll
            for (int j = 0; j < 4; j++) { S[i][j] = __expf(S[i][j] - mnew); rs += S[i][j]; }
#pragma unroll
            for (int off = 8; off > 0; off >>= 1)
                rs += __shfl_xor_sync(0xffffffffu, rs, off);
            l_run[i] = l_run[i] * corr + rs;
            m_run[i] = mnew;
#pragma unroll
            for (int j = 0; j < 4; j++) { O[i][j] *= corr; Ps[(4*my + i) * 68 + 4*sx + j] = S[i][j]; }
        }
        __syncthreads();   // Ps fully written
        // O += P @ V
#pragma unroll 4
        for (int s4 = 0; s4 < 16; s4++) {
            float pa[4][4];
#pragma unroll
            for (int i = 0; i < 4; i++) {
                float4 p4 = *(const float4*)&Ps[(4*my + i) * 68 + 4 * s4];
                pa[i][0] = p4.x; pa[i][1] = p4.y; pa[i][2] = p4.z; pa[i][3] = p4.w;
            }
#pragma unroll
            for (int k = 0; k < 4; k++) {
                float4 v4 = *(const float4*)&Vs[(4*s4 + k) * 68 + 4 * sx];
                float va[4] = {v4.x, v4.y, v4.z, v4.w};
#pragma unroll
                for (int i = 0; i < 4; i++)
#pragma unroll
                    for (int j = 0; j < 4; j++) O[i][j] += pa[i][k] * va[j];
            }
        }
    }

    // normalize + write context in [t,b,e] layout
#pragma unroll
    for (int i = 0; i < 4; i++) {
        float inv = 1.f / l_run[i];
        float4 o;
        o.x = O[i][0] * inv; o.y = O[i][1] * inv;
        o.z = O[i][2] * inv; o.w = O[i][3] * inv;
        *(float4*)&g_ctx[((size_t)(t0 + 4*my + i) * B_ + b) * E_ + h * HD_ + 4 * sx] = o;
    }
}

// ---------------------------------------------------------------------------
// kernel_launch: QKV proj -> fused attention -> out proj (single stream, graph-capturable)
// One-time host init for symbol addresses / smem attribute (outside capture-hot path).
// ---------------------------------------------------------------------------
static float* s_qkv = nullptr;
static float* s_ctx = nullptr;
static bool s_init = false;
static const int s_attn_smem = (2 * 64 * 64 + 2 * 64 * 68) * (int)sizeof(float);  // 67584 B

extern "C" void kernel_launch(void* const* d_in, const int* in_sizes, int n_in,
                              void* d_out, int out_size)
{
    const float* query = (const float*)d_in[0];
    const float* dist  = (const float*)d_in[1];
    const float* w_in  = (const float*)d_in[2];
    const float* b_in  = (const float*)d_in[3];
    const float* w_out = (const float*)d_in[4];
    const float* b_out = (const float*)d_in[5];
    float* out = (float*)d_out;

    if (!s_init) {
        cudaGetSymbolAddress((void**)&s_qkv, g_qkv);
        cudaGetSymbolAddress((void**)&s_ctx, g_ctx);
        cudaFuncSetAttribute(attn_kernel, cudaFuncAttributeMaxDynamicSharedMemorySize, s_attn_smem);
        s_init = true;
    }

    // 1) QKV projection: [4096,512] x [1536,512]^T -> g_qkv [4096,1536]
    gemm_nt_bias<<<dim3(64, 24), 256>>>(query, w_in, b_in, s_qkv, E_, E3_);

    // 2) fused biased attention -> g_ctx [4096,512] (already in [t,b,e] order)
    attn_kernel<<<dim3(16, 32), 256, s_attn_smem>>>(dist);

    // 3) output projection: [4096,512] x [512,512]^T -> out [4096,512]
    gemm_nt_bias<<<dim3(64, 8), 256>>>(s_ctx, w_out, b_out, out, E_, E_);
}

// round 7
// speedup vs baseline: 1.3718x; 1.3718x over previous
#include <cuda_runtime.h>
#include <cuda_bf16.h>
#include <cstdint>

// Problem constants
#define T_ 1024
#define B_ 4
#define E_ 512
#define H_ 8
#define HD_ 64
#define E3_ 1536

// Scratch (static device globals — allocation-free contract)
__device__ float g_qkv[T_ * B_ * E3_];   // [t,b, 3E]
__device__ float g_ctx[T_ * B_ * E_];    // [t,b, E]
__device__ __nv_bfloat16 g_q_hi[T_ * B_ * E_],  g_q_lo[T_ * B_ * E_];
__device__ __nv_bfloat16 g_wi_hi[E3_ * E_],     g_wi_lo[E3_ * E_];
__device__ __nv_bfloat16 g_wo_hi[E_ * E_],      g_wo_lo[E_ * E_];
__device__ __nv_bfloat16 g_c_hi[T_ * B_ * E_],  g_c_lo[T_ * B_ * E_];

// ---------------------------------------------------------------------------
// helpers: cp.async, ldmatrix, bf16 mma (all plain-sm_103-legal, sm_80+ ISA)
// ---------------------------------------------------------------------------
__device__ __forceinline__ uint32_t smem_u32(const void* p) {
    uint32_t a;
    asm("{ .reg .u64 t; cvta.to.shared.u64 t, %1; cvt.u32.u64 %0, t; }" : "=r"(a) : "l"(p));
    return a;
}
#define CP_ASYNC16(dst, src) \
    asm volatile("cp.async.cg.shared.global [%0], [%1], 16;" :: "r"(dst), "l"(src))
#define CP_COMMIT() asm volatile("cp.async.commit_group;" ::: "memory")
#define CP_WAIT(n)  asm volatile("cp.async.wait_group %0;" :: "n"(n) : "memory")

__device__ __forceinline__ void ldm_x4(uint32_t* r, uint32_t addr) {
    asm volatile("ldmatrix.sync.aligned.m8n8.x4.shared.b16 {%0,%1,%2,%3}, [%4];"
                 : "=r"(r[0]), "=r"(r[1]), "=r"(r[2]), "=r"(r[3]) : "r"(addr));
}
__device__ __forceinline__ void mma_bf16(float* c, const uint32_t* a, const uint32_t* b) {
    asm volatile("mma.sync.aligned.m16n8k16.row.col.f32.bf16.bf16.f32 "
                 "{%0,%1,%2,%3}, {%4,%5,%6,%7}, {%8,%9}, {%0,%1,%2,%3};"
                 : "+f"(c[0]), "+f"(c[1]), "+f"(c[2]), "+f"(c[3])
                 : "r"(a[0]), "r"(a[1]), "r"(a[2]), "r"(a[3]), "r"(b[0]), "r"(b[1]));
}

// ---------------------------------------------------------------------------
// split: x -> bf16 hi + bf16 lo  (exact to ~2^-16 relative)
// ---------------------------------------------------------------------------
__global__ void split_bf16_kernel(const float* __restrict__ x,
                                  __nv_bfloat16* __restrict__ hi,
                                  __nv_bfloat16* __restrict__ lo, int n4)
{
    int i = blockIdx.x * blockDim.x + threadIdx.x;
    if (i >= n4) return;
    float4 v = ((const float4*)x)[i];
    __nv_bfloat16 h0 = __float2bfloat16(v.x), h1 = __float2bfloat16(v.y);
    __nv_bfloat16 h2 = __float2bfloat16(v.z), h3 = __float2bfloat16(v.w);
    __nv_bfloat16 l0 = __float2bfloat16(v.x - __bfloat162float(h0));
    __nv_bfloat16 l1 = __float2bfloat16(v.y - __bfloat162float(h1));
    __nv_bfloat16 l2 = __float2bfloat16(v.z - __bfloat162float(h2));
    __nv_bfloat16 l3 = __float2bfloat16(v.w - __bfloat162float(h3));
    __nv_bfloat162 a, b;
    a.x = h0; a.y = h1; b.x = h2; b.y = h3;
    ((__nv_bfloat162*)hi)[2*i] = a; ((__nv_bfloat162*)hi)[2*i+1] = b;
    a.x = l0; a.y = l1; b.x = l2; b.y = l3;
    ((__nv_bfloat162*)lo)[2*i] = a; ((__nv_bfloat162*)lo)[2*i+1] = b;
}

// ---------------------------------------------------------------------------
// HMMA GEMM: C[m,n] = bias[n] + sum_k A[m,k] W[n,k], split-bf16 (3 products
// per tile load: hh + hl + lh). BM=BN=128, BK=32, K=512. 8 warps (4x2), warp
// tile 32x64. cp.async double-buffered stages. smem rows padded to 80B
// (conflict-free ldmatrix).
// ---------------------------------------------------------------------------
__global__ __launch_bounds__(256, 1)
void gemm_mma(const __nv_bfloat16* __restrict__ Ah, const __nv_bfloat16* __restrict__ Al,
              const __nv_bfloat16* __restrict__ Bh, const __nv_bfloat16* __restrict__ Bl,
              const float* __restrict__ bias, float* __restrict__ C, int ldc)
{
    constexpr int K = 512, BK = 32, CH = K / BK;   // 16 chunks
    constexpr int LDT = BK + 8;                    // 40 bf16 = 80 B row stride
    constexpr int TILE_B = 128 * LDT * 2;          // 10240 bytes per tile
    constexpr int STAGE_B = 4 * TILE_B;            // Ah|Al|Bh|Bl = 40960 B

    extern __shared__ char smem[];
    const uint32_t sbase = smem_u32(smem);
    const int tid = threadIdx.x, lane = tid & 31, wid = tid >> 5;
    const int wm = wid & 3, wn = wid >> 2;         // 4x2 warp grid
    const int m0 = blockIdx.x * 128, n0 = blockIdx.y * 128;

    float acc[2][8][4];
#pragma unroll
    for (int i = 0; i < 2; i++)
#pragma unroll
        for (int j = 0; j < 8; j++)
#pragma unroll
            for (int q = 0; q < 4; q++) acc[i][j][q] = 0.f;

    auto load_chunk = [&](int c, int stage) {
        const int kk = c * BK;
        const uint32_t so = sbase + stage * STAGE_B;
#pragma unroll
        for (int q = 0; q < 2; q++) {
            int idx = q * 256 + tid;
            int r = idx >> 2, s = idx & 3;         // r: 0..127 row, s: 16B segment
            uint32_t d = so + (uint32_t)(r * LDT + s * 8) * 2;
            CP_ASYNC16(d + 0 * TILE_B, Ah + (size_t)(m0 + r) * K + kk + s * 8);
            CP_ASYNC16(d + 1 * TILE_B, Al + (size_t)(m0 + r) * K + kk + s * 8);
            CP_ASYNC16(d + 2 * TILE_B, Bh + (size_t)(n0 + r) * K + kk + s * 8);
            CP_ASYNC16(d + 3 * TILE_B, Bl + (size_t)(n0 + r) * K + kk + s * 8);
        }
    };

    load_chunk(0, 0);
    CP_COMMIT();

    for (int c = 0; c < CH; c++) {
        if (c + 1 < CH) { load_chunk(c + 1, (c + 1) & 1); CP_COMMIT(); CP_WAIT(1); }
        else            { CP_WAIT(0); }
        __syncthreads();

        const uint32_t so = sbase + (c & 1) * STAGE_B;
#pragma unroll
        for (int ks = 0; ks < BK; ks += 16) {
            uint32_t a_h[2][4], a_l[2][4];
#pragma unroll
            for (int mi = 0; mi < 2; mi++) {
                int row = wm * 32 + mi * 16 + (lane & 15);
                int col = ks + ((lane >> 4) << 3);
                uint32_t ad = so + (uint32_t)(row * LDT + col) * 2;
                ldm_x4(a_h[mi], ad);
                ldm_x4(a_l[mi], ad + TILE_B);
            }
#pragma unroll
            for (int nj = 0; nj < 4; nj++) {
                int row = wn * 64 + nj * 16 + (lane & 7) + ((lane >> 4) << 3);
                int col = ks + (((lane >> 3) & 1) << 3);
                uint32_t bd = so + 2 * TILE_B + (uint32_t)(row * LDT + col) * 2;
                uint32_t b_h[4], b_l[4];
                ldm_x4(b_h, bd);
                ldm_x4(b_l, bd + TILE_B);
#pragma unroll
                for (int mi = 0; mi < 2; mi++) {
                    mma_bf16(acc[mi][nj*2],   a_h[mi], b_h);
                    mma_bf16(acc[mi][nj*2],   a_h[mi], b_l);
                    mma_bf16(acc[mi][nj*2],   a_l[mi], b_h);
                    mma_bf16(acc[mi][nj*2+1], a_h[mi], b_h + 2);
                    mma_bf16(acc[mi][nj*2+1], a_h[mi], b_l + 2);
                    mma_bf16(acc[mi][nj*2+1], a_l[mi], b_h + 2);
                }
            }
        }
        __syncthreads();
    }

    // epilogue: D frag (c0,c1)->(row,2c),(row,2c+1); (c2,c3)->row+8
#pragma unroll
    for (int mi = 0; mi < 2; mi++) {
#pragma unroll
        for (int n8 = 0; n8 < 8; n8++) {
            int r  = m0 + wm * 32 + mi * 16 + (lane >> 2);
            int cc = n0 + wn * 64 + n8 * 8 + (lane & 3) * 2;
            float b0 = __ldg(&bias[cc]), b1 = __ldg(&bias[cc + 1]);
            float2 v0 = {acc[mi][n8][0] + b0, acc[mi][n8][1] + b1};
            float2 v1 = {acc[mi][n8][2] + b0, acc[mi][n8][3] + b1};
            *(float2*)&C[(size_t)r * ldc + cc] = v0;
            *(float2*)&C[(size_t)(r + 8) * ldc + cc] = v1;
        }
    }
}

// ---------------------------------------------------------------------------
// Fused attention (unchanged, validated round 4): fp32 SIMT flash attention.
// ---------------------------------------------------------------------------
__global__ __launch_bounds__(256)
void attn_kernel(const float* __restrict__ dist)
{
    extern __shared__ float sm[];
    float* Qs = sm;                 // [64][64]
    float* Ks = sm + 64 * 64;       // [64][64]
    float* Vs = sm + 2 * 64 * 64;   // [64][68]
    float* Ps = Vs + 64 * 68;       // [64][68]

    const int qt = blockIdx.x;
    const int bh = blockIdx.y;
    const int b = bh >> 3, h = bh & 7;
    const int t0 = qt * 64;
    const int tid = threadIdx.x;
    const int my = tid >> 4, sx = tid & 15;
    const float scale = 0.125f;

#pragma unroll
    for (int p = 0; p < 4; p++) {
        int idx = p * 256 + tid;
        int r = idx & 63, d4 = idx >> 6;
        float4 v = *(const float4*)&g_qkv[((size_t)(t0 + r) * B_ + b) * E3_ + h * HD_ + 4 * d4];
        Qs[(4*d4+0)*64 + r] = v.x * scale; Qs[(4*d4+1)*64 + r] = v.y * scale;
        Qs[(4*d4+2)*64 + r] = v.z * scale; Qs[(4*d4+3)*64 + r] = v.w * scale;
    }

    float m_run[4] = {-1e30f, -1e30f, -1e30f, -1e30f};
    float l_run[4] = {0.f, 0.f, 0.f, 0.f};
    float O[4][4];
#pragma unroll
    for (int i = 0; i < 4; i++)
#pragma unroll
        for (int j = 0; j < 4; j++) O[i][j] = 0.f;

    for (int st = 0; st < 16; st++) {
        const int s0 = st * 64;
        __syncthreads();
#pragma unroll
        for (int p = 0; p < 4; p++) {
            int idx = p * 256 + tid;
            int r = idx & 63, d4 = idx >> 6;
            float4 kv = *(const float4*)&g_qkv[((size_t)(s0 + r) * B_ + b) * E3_ + E_ + h * HD_ + 4 * d4];
            Ks[(4*d4+0)*64 + r] = kv.x; Ks[(4*d4+1)*64 + r] = kv.y;
            Ks[(4*d4+2)*64 + r] = kv.z; Ks[(4*d4+3)*64 + r] = kv.w;
        }
#pragma unroll
        for (int p = 0; p < 4; p++) {
            int idx = p * 256 + tid;
            int d4 = idx & 15, s = idx >> 4;
            float4 vv = *(const float4*)&g_qkv[((size_t)(s0 + s) * B_ + b) * E3_ + 2 * E_ + h * HD_ + 4 * d4];
            *(float4*)&Vs[s * 68 + 4 * d4] = vv;
        }
        __syncthreads();

        float S[4][4];
#pragma unroll
        for (int i = 0; i < 4; i++)
#pragma unroll
            for (int j = 0; j < 4; j++) S[i][j] = 0.f;
#pragma unroll 8
        for (int d = 0; d < 64; d++) {
            float4 q4 = *(const float4*)&Qs[d * 64 + 4 * my];
            float4 k4 = *(const float4*)&Ks[d * 64 + 4 * sx];
            float qa[4] = {q4.x, q4.y, q4.z, q4.w};
            float ka[4] = {k4.x, k4.y, k4.z, k4.w};
#pragma unroll
            for (int i = 0; i < 4; i++)
#pragma unroll
                for (int j = 0; j < 4; j++) S[i][j] += qa[i] * ka[j];
        }
        {
            const size_t base = (((size_t)b * T_ + (t0 + 4 * my)) * T_ + (s0 + 4 * sx)) * H_ + h;
#pragma unroll
            for (int i = 0; i < 4; i++)
#pragma unroll
                for (int j = 0; j < 4; j++)
                    S[i][j] += __ldg(&dist[base + ((size_t)i * T_ + j) * H_]);
        }
#pragma unroll
        for (int i = 0; i < 4; i++) {
            float mx = fmaxf(fmaxf(S[i][0], S[i][1]), fmaxf(S[i][2], S[i][3]));
#pragma unroll
            for (int off = 8; off > 0; off >>= 1)
                mx = fmaxf(mx, __shfl_xor_sync(0xffffffffu, mx, off));
            float mnew = fmaxf(m_run[i], mx);
            float corr = __expf(m_run[i] - mnew);
            float rs = 0.f;
#pragma unroll
            for (int j = 0; j < 4; j++) { S[i][j] = __expf(S[i][j] - mnew); rs += S[i][j]; }
#pragma unroll
            for (int off = 8; off > 0; off >>= 1)
                rs += __shfl_xor_sync(0xffffffffu, rs, off);
            l_run[i] = l_run[i] * corr + rs;
            m_run[i] = mnew;
#pragma unroll
            for (int j = 0; j < 4; j++) { O[i][j] *= corr; Ps[(4*my + i) * 68 + 4*sx + j] = S[i][j]; }
        }
        __syncthreads();
#pragma unroll 4
        for (int s4 = 0; s4 < 16; s4++) {
            float pa[4][4];
#pragma unroll
            for (int i = 0; i < 4; i++) {
                float4 p4 = *(const float4*)&Ps[(4*my + i) * 68 + 4 * s4];
                pa[i][0] = p4.x; pa[i][1] = p4.y; pa[i][2] = p4.z; pa[i][3] = p4.w;
            }
#pragma unroll
            for (int k = 0; k < 4; k++) {
                float4 v4 = *(const float4*)&Vs[(4*s4 + k) * 68 + 4 * sx];
                float va[4] = {v4.x, v4.y, v4.z, v4.w};
#pragma unroll
                for (int i = 0; i < 4; i++)
#pragma unroll
                    for (int j = 0; j < 4; j++) O[i][j] += pa[i][k] * va[j];
            }
        }
    }

#pragma unroll
    for (int i = 0; i < 4; i++) {
        float inv = 1.f / l_run[i];
        float4 o;
        o.x = O[i][0] * inv; o.y = O[i][1] * inv;
        o.z = O[i][2] * inv; o.w = O[i][3] * inv;
        *(float4*)&g_ctx[((size_t)(t0 + 4*my + i) * B_ + b) * E_ + h * HD_ + 4 * sx] = o;
    }
}

// ---------------------------------------------------------------------------
// kernel_launch
// ---------------------------------------------------------------------------
static float* s_qkv = nullptr;
static float* s_ctx = nullptr;
static __nv_bfloat16 *s_qh, *s_ql, *s_wih, *s_wil, *s_woh, *s_wol, *s_ch, *s_cl;
static bool s_init = false;
static const int s_attn_smem = (2 * 64 * 64 + 2 * 64 * 68) * (int)sizeof(float);   // 67584
static const int GEMM_SMEM = 2 * 4 * 128 * 40 * 2;                                  // 81920

extern "C" void kernel_launch(void* const* d_in, const int* in_sizes, int n_in,
                              void* d_out, int out_size)
{
    const float* query = (const float*)d_in[0];
    const float* dist  = (const float*)d_in[1];
    const float* w_in  = (const float*)d_in[2];
    const float* b_in  = (const float*)d_in[3];
    const float* w_out = (const float*)d_in[4];
    const float* b_out = (const float*)d_in[5];
    float* out = (float*)d_out;

    if (!s_init) {
        cudaGetSymbolAddress((void**)&s_qkv, g_qkv);
        cudaGetSymbolAddress((void**)&s_ctx, g_ctx);
        cudaGetSymbolAddress((void**)&s_qh,  g_q_hi);  cudaGetSymbolAddress((void**)&s_ql,  g_q_lo);
        cudaGetSymbolAddress((void**)&s_wih, g_wi_hi); cudaGetSymbolAddress((void**)&s_wil, g_wi_lo);
        cudaGetSymbolAddress((void**)&s_woh, g_wo_hi); cudaGetSymbolAddress((void**)&s_wol, g_wo_lo);
        cudaGetSymbolAddress((void**)&s_ch,  g_c_hi);  cudaGetSymbolAddress((void**)&s_cl,  g_c_lo);
        cudaFuncSetAttribute(attn_kernel, cudaFuncAttributeMaxDynamicSharedMemorySize, s_attn_smem);
        cudaFuncSetAttribute(gemm_mma, cudaFuncAttributeMaxDynamicSharedMemorySize, GEMM_SMEM);
        s_init = true;
    }

    // splits (query + both weights)
    split_bf16_kernel<<<(T_*B_*E_/4 + 255)/256, 256>>>(query, s_qh, s_ql, T_*B_*E_/4);
    split_bf16_kernel<<<(E3_*E_/4 + 255)/256, 256>>>(w_in, s_wih, s_wil, E3_*E_/4);
    split_bf16_kernel<<<(E_*E_/4 + 255)/256, 256>>>(w_out, s_woh, s_wol, E_*E_/4);

    // 1) QKV projection (HMMA): [4096,512] x [1536,512]^T -> g_qkv
    gemm_mma<<<dim3(32, 12), 256, GEMM_SMEM>>>(s_qh, s_ql, s_wih, s_wil, b_in, s_qkv, E3_);

    // 2) fused biased attention -> g_ctx
    attn_kernel<<<dim3(16, 32), 256, s_attn_smem>>>(dist);

    // 3) split ctx, output projection (HMMA) -> out
    split_bf16_kernel<<<(T_*B_*E_/4 + 255)/256, 256>>>(s_ctx, s_ch, s_cl, T_*B_*E_/4);
    gemm_mma<<<dim3(32, 4), 256, GEMM_SMEM>>>(s_ch, s_cl, s_woh, s_wol, b_out, out, E_);
}

// round 9
// speedup vs baseline: 2.8335x; 2.0656x over previous
#include <cuda_runtime.h>
#include <cuda_bf16.h>
#include <cstdint>

// Problem constants
#define T_ 1024
#define B_ 4
#define E_ 512
#define H_ 8
#define HD_ 64
#define E3_ 1536

// Scratch (static device globals — allocation-free contract)
__device__ float g_qkv[T_ * B_ * E3_];   // [t,b, 3E]
__device__ float g_ctx[T_ * B_ * E_];    // [t,b, E]
__device__ __nv_bfloat16 g_q_hi[T_ * B_ * E_],  g_q_lo[T_ * B_ * E_];
__device__ __nv_bfloat16 g_wi_hi[E3_ * E_],     g_wi_lo[E3_ * E_];
__device__ __nv_bfloat16 g_wo_hi[E_ * E_],      g_wo_lo[E_ * E_];
__device__ __nv_bfloat16 g_c_hi[T_ * B_ * E_],  g_c_lo[T_ * B_ * E_];
__device__ __nv_bfloat16 g_qkv_h[T_ * B_ * E3_], g_qkv_l[T_ * B_ * E3_];

// ---------------------------------------------------------------------------
// helpers (plain-sm_103-legal, sm_80+ ISA)
// ---------------------------------------------------------------------------
__device__ __forceinline__ uint32_t smem_u32(const void* p) {
    uint32_t a;
    asm("{ .reg .u64 t; cvta.to.shared.u64 t, %1; cvt.u32.u64 %0, t; }" : "=r"(a) : "l"(p));
    return a;
}
#define CP_ASYNC16(dst, src) \
    asm volatile("cp.async.cg.shared.global [%0], [%1], 16;" :: "r"(dst), "l"(src))
#define CP_COMMIT() asm volatile("cp.async.commit_group;" ::: "memory")
#define CP_WAIT(n)  asm volatile("cp.async.wait_group %0;" :: "n"(n) : "memory")

__device__ __forceinline__ void ldm_x4(uint32_t* r, uint32_t addr) {
    asm volatile("ldmatrix.sync.aligned.m8n8.x4.shared.b16 {%0,%1,%2,%3}, [%4];"
                 : "=r"(r[0]), "=r"(r[1]), "=r"(r[2]), "=r"(r[3]) : "r"(addr));
}
__device__ __forceinline__ void ldm_x4_t(uint32_t* r, uint32_t addr) {
    asm volatile("ldmatrix.sync.aligned.m8n8.x4.trans.shared.b16 {%0,%1,%2,%3}, [%4];"
                 : "=r"(r[0]), "=r"(r[1]), "=r"(r[2]), "=r"(r[3]) : "r"(addr));
}
__device__ __forceinline__ void mma_bf16(float* c, const uint32_t* a, const uint32_t* b) {
    asm volatile("mma.sync.aligned.m16n8k16.row.col.f32.bf16.bf16.f32 "
                 "{%0,%1,%2,%3}, {%4,%5,%6,%7}, {%8,%9}, {%0,%1,%2,%3};"
                 : "+f"(c[0]), "+f"(c[1]), "+f"(c[2]), "+f"(c[3])
                 : "r"(a[0]), "r"(a[1]), "r"(a[2]), "r"(a[3]), "r"(b[0]), "r"(b[1]));
}
__device__ __forceinline__ void pack2(float x, float y, uint32_t& hi, uint32_t& lo) {
    __nv_bfloat162 hv = __floats2bfloat162_rn(x, y);
    float rx = x - __bfloat162float(hv.x);
    float ry = y - __bfloat162float(hv.y);
    __nv_bfloat162 lv = __floats2bfloat162_rn(rx, ry);
    hi = *reinterpret_cast<uint32_t*>(&hv);
    lo = *reinterpret_cast<uint32_t*>(&lv);
}

// ---------------------------------------------------------------------------
// split: x -> bf16 hi + bf16 lo
// ---------------------------------------------------------------------------
__global__ void split_bf16_kernel(const float* __restrict__ x,
                                  __nv_bfloat16* __restrict__ hi,
                                  __nv_bfloat16* __restrict__ lo, int n4)
{
    int i = blockIdx.x * blockDim.x + threadIdx.x;
    if (i >= n4) return;
    float4 v = ((const float4*)x)[i];
    __nv_bfloat16 h0 = __float2bfloat16(v.x), h1 = __float2bfloat16(v.y);
    __nv_bfloat16 h2 = __float2bfloat16(v.z), h3 = __float2bfloat16(v.w);
    __nv_bfloat16 l0 = __float2bfloat16(v.x - __bfloat162float(h0));
    __nv_bfloat16 l1 = __float2bfloat16(v.y - __bfloat162float(h1));
    __nv_bfloat16 l2 = __float2bfloat16(v.z - __bfloat162float(h2));
    __nv_bfloat16 l3 = __float2bfloat16(v.w - __bfloat162float(h3));
    __nv_bfloat162 a, b;
    a.x = h0; a.y = h1; b.x = h2; b.y = h3;
    ((__nv_bfloat162*)hi)[2*i] = a; ((__nv_bfloat162*)hi)[2*i+1] = b;
    a.x = l0; a.y = l1; b.x = l2; b.y = l3;
    ((__nv_bfloat162*)lo)[2*i] = a; ((__nv_bfloat162*)lo)[2*i+1] = b;
}

// ---------------------------------------------------------------------------
// HMMA GEMM (validated round 7): C = bias + A W^T, split-bf16 3-pass
// ---------------------------------------------------------------------------
__global__ __launch_bounds__(256, 1)
void gemm_mma(const __nv_bfloat16* __restrict__ Ah, const __nv_bfloat16* __restrict__ Al,
              const __nv_bfloat16* __restrict__ Bh, const __nv_bfloat16* __restrict__ Bl,
              const float* __restrict__ bias, float* __restrict__ C, int ldc)
{
    constexpr int K = 512, BK = 32, CH = K / BK;
    constexpr int LDT = BK + 8;
    constexpr int TILE_B = 128 * LDT * 2;
    constexpr int STAGE_B = 4 * TILE_B;

    extern __shared__ char smem[];
    const uint32_t sbase = smem_u32(smem);
    const int tid = threadIdx.x, lane = tid & 31, wid = tid >> 5;
    const int wm = wid & 3, wn = wid >> 2;
    const int m0 = blockIdx.x * 128, n0 = blockIdx.y * 128;

    float acc[2][8][4];
#pragma unroll
    for (int i = 0; i < 2; i++)
#pragma unroll
        for (int j = 0; j < 8; j++)
#pragma unroll
            for (int q = 0; q < 4; q++) acc[i][j][q] = 0.f;

    auto load_chunk = [&](int c, int stage) {
        const int kk = c * BK;
        const uint32_t so = sbase + stage * STAGE_B;
#pragma unroll
        for (int q = 0; q < 2; q++) {
            int idx = q * 256 + tid;
            int r = idx >> 2, s = idx & 3;
            uint32_t d = so + (uint32_t)(r * LDT + s * 8) * 2;
            CP_ASYNC16(d + 0 * TILE_B, Ah + (size_t)(m0 + r) * K + kk + s * 8);
            CP_ASYNC16(d + 1 * TILE_B, Al + (size_t)(m0 + r) * K + kk + s * 8);
            CP_ASYNC16(d + 2 * TILE_B, Bh + (size_t)(n0 + r) * K + kk + s * 8);
            CP_ASYNC16(d + 3 * TILE_B, Bl + (size_t)(n0 + r) * K + kk + s * 8);
        }
    };

    load_chunk(0, 0);
    CP_COMMIT();

    for (int c = 0; c < CH; c++) {
        if (c + 1 < CH) { load_chunk(c + 1, (c + 1) & 1); CP_COMMIT(); CP_WAIT(1); }
        else            { CP_WAIT(0); }
        __syncthreads();

        const uint32_t so = sbase + (c & 1) * STAGE_B;
#pragma unroll
        for (int ks = 0; ks < BK; ks += 16) {
            uint32_t a_h[2][4], a_l[2][4];
#pragma unroll
            for (int mi = 0; mi < 2; mi++) {
                int row = wm * 32 + mi * 16 + (lane & 15);
                int col = ks + ((lane >> 4) << 3);
                uint32_t ad = so + (uint32_t)(row * LDT + col) * 2;
                ldm_x4(a_h[mi], ad);
                ldm_x4(a_l[mi], ad + TILE_B);
            }
#pragma unroll
            for (int nj = 0; nj < 4; nj++) {
                int row = wn * 64 + nj * 16 + (lane & 7) + ((lane >> 4) << 3);
                int col = ks + (((lane >> 3) & 1) << 3);
                uint32_t bd = so + 2 * TILE_B + (uint32_t)(row * LDT + col) * 2;
                uint32_t b_h[4], b_l[4];
                ldm_x4(b_h, bd);
                ldm_x4(b_l, bd + TILE_B);
#pragma unroll
                for (int mi = 0; mi < 2; mi++) {
                    mma_bf16(acc[mi][nj*2],   a_h[mi], b_h);
                    mma_bf16(acc[mi][nj*2],   a_h[mi], b_l);
                    mma_bf16(acc[mi][nj*2],   a_l[mi], b_h);
                    mma_bf16(acc[mi][nj*2+1], a_h[mi], b_h + 2);
                    mma_bf16(acc[mi][nj*2+1], a_h[mi], b_l + 2);
                    mma_bf16(acc[mi][nj*2+1], a_l[mi], b_h + 2);
                }
            }
        }
        __syncthreads();
    }

#pragma unroll
    for (int mi = 0; mi < 2; mi++) {
#pragma unroll
        for (int n8 = 0; n8 < 8; n8++) {
            int r  = m0 + wm * 32 + mi * 16 + (lane >> 2);
            int cc = n0 + wn * 64 + n8 * 8 + (lane & 3) * 2;
            float b0 = __ldg(&bias[cc]), b1 = __ldg(&bias[cc + 1]);
            float2 v0 = {acc[mi][n8][0] + b0, acc[mi][n8][1] + b1};
            float2 v1 = {acc[mi][n8][2] + b0, acc[mi][n8][3] + b1};
            *(float2*)&C[(size_t)r * ldc + cc] = v0;
            *(float2*)&C[(size_t)(r + 8) * ldc + cc] = v1;
        }
    }
}

// ---------------------------------------------------------------------------
// HMMA flash attention with bias. CTA = (h, b, 128-row q tile); 8 warps x 16
// q-rows. Split-bf16 3-pass for QK^T and PV. K/V double-buffered cp.async.
// ---------------------------------------------------------------------------
__global__ __launch_bounds__(256)
void attn_mma(const float* __restrict__ dist)
{
    constexpr int LDA = 72;               // bf16/row (144 B), conflict-free ldmatrix
    constexpr int TB  = 128 * LDA * 2;    // 18432 B per tile
    constexpr uint32_t QH = 0, ST0 = 2 * TB;
    constexpr uint32_t STG = 4 * TB;      // Kh|Kl|Vh|Vl = 73728 B

    extern __shared__ char smem[];
    const uint32_t sb = smem_u32(smem);
    const int tid = threadIdx.x, lane = tid & 31, w = tid >> 5;
    const int h = blockIdx.x, b = blockIdx.y >> 3, qt = blockIdx.y & 7;
    const int t0 = qt * 128;

    // Q hi/lo -> smem (once)
#pragma unroll
    for (int i = 0; i < 4; i++) {
        int idx = i * 256 + tid;
        int r = idx >> 3, sg = idx & 7;
        size_t off = (size_t)(t0 + r) * (B_ * E3_) + b * E3_ + h * 64 + sg * 8;
        *(uint4*)(smem + QH + r * 144 + sg * 16)      = *(const uint4*)(g_qkv_h + off);
        *(uint4*)(smem + QH + TB + r * 144 + sg * 16) = *(const uint4*)(g_qkv_l + off);
    }

    auto load_stage = [&](int st) {
        const int s0 = st * 128;
        const uint32_t so = sb + ST0 + (uint32_t)(st & 1) * STG;
#pragma unroll
        for (int i = 0; i < 16; i++) {
            int idx = i * 256 + tid;            // 0..4095
            int tile = idx >> 10;               // Kh,Kl,Vh,Vl
            int seg = idx & 1023;
            int r = seg >> 3, sg = seg & 7;
            const __nv_bfloat16* src = (tile & 1) ? g_qkv_l : g_qkv_h;
            int vk = (tile >> 1) ? 2 * E_ : E_;
            size_t off = (size_t)(s0 + r) * (B_ * E3_) + b * E3_ + vk + h * 64 + sg * 8;
            CP_ASYNC16(so + (uint32_t)tile * TB + (uint32_t)(r * 144 + sg * 16), src + off);
        }
    };

    float Oa[8][4];
#pragma unroll
    for (int j = 0; j < 8; j++)
#pragma unroll
        for (int q = 0; q < 4; q++) Oa[j][q] = 0.f;
    float mA = -1e30f, mB = -1e30f, lA = 0.f, lB = 0.f;

    load_stage(0);
    CP_COMMIT();

    for (int st = 0; st < 8; st++) {
        if (st < 7) { load_stage(st + 1); CP_COMMIT(); CP_WAIT(1); }
        else        { CP_WAIT(0); }
        __syncthreads();
        const uint32_t so = sb + ST0 + (uint32_t)(st & 1) * STG;
        const int s0 = st * 128;

        // Q fragments for this warp (reused across all 8 s-groups)
        uint32_t Qh_f[4][4], Ql_f[4][4];
#pragma unroll
        for (int ch = 0; ch < 4; ch++) {
            int row = w * 16 + (lane & 15);
            int col = ch * 16 + ((lane >> 4) << 3);
            uint32_t ad = sb + QH + (uint32_t)(row * LDA + col) * 2;
            ldm_x4(Qh_f[ch], ad);
            ldm_x4(Ql_f[ch], ad + TB);
        }

        float Sf[16][4];
#pragma unroll
        for (int g = 0; g < 8; g++) {
            // bias loads for this s16 group (issued before the mma burst)
            int qA = t0 + w * 16 + (lane >> 2);
            int sc0 = s0 + g * 16 + ((lane & 3) << 1);
            size_t db = (((size_t)b * T_ + qA) * T_ + sc0) * H_ + h;
            float bb0 = __ldg(dist + db),            bb1 = __ldg(dist + db + 8);
            float bb2 = __ldg(dist + db + 65536),    bb3 = __ldg(dist + db + 65536 + 8);
            float bb4 = __ldg(dist + db + 64),       bb5 = __ldg(dist + db + 72);
            float bb6 = __ldg(dist + db + 65536+64), bb7 = __ldg(dist + db + 65536+72);
#pragma unroll
            for (int q = 0; q < 4; q++) { Sf[2*g][q] = 0.f; Sf[2*g+1][q] = 0.f; }
#pragma unroll
            for (int ch = 0; ch < 4; ch++) {
                // B-style lane map (matches validated gemm_mma): regs =
                // (s0-7/k0-7, s0-7/k8-15, s8-15/k0-7, s8-15/k8-15)
                int row = g * 16 + (lane & 7) + ((lane >> 4) << 3);
                int col = ch * 16 + (((lane >> 3) & 1) << 3);
                uint32_t kd = so + (uint32_t)(row * LDA + col) * 2;
                uint32_t Kh4[4], Kl4[4];
                ldm_x4(Kh4, kd);
                ldm_x4(Kl4, kd + TB);
                mma_bf16(Sf[2*g],   Qh_f[ch], Kh4);
                mma_bf16(Sf[2*g],   Qh_f[ch], Kl4);
                mma_bf16(Sf[2*g],   Ql_f[ch], Kh4);
                mma_bf16(Sf[2*g+1], Qh_f[ch], Kh4 + 2);
                mma_bf16(Sf[2*g+1], Qh_f[ch], Kl4 + 2);
                mma_bf16(Sf[2*g+1], Ql_f[ch], Kh4 + 2);
            }
            Sf[2*g][0]   = Sf[2*g][0]   * 0.125f + bb0;
            Sf[2*g][1]   = Sf[2*g][1]   * 0.125f + bb1;
            Sf[2*g][2]   = Sf[2*g][2]   * 0.125f + bb2;
            Sf[2*g][3]   = Sf[2*g][3]   * 0.125f + bb3;
            Sf[2*g+1][0] = Sf[2*g+1][0] * 0.125f + bb4;
            Sf[2*g+1][1] = Sf[2*g+1][1] * 0.125f + bb5;
            Sf[2*g+1][2] = Sf[2*g+1][2] * 0.125f + bb6;
            Sf[2*g+1][3] = Sf[2*g+1][3] * 0.125f + bb7;
        }

        // online softmax (row A = q, row B = q+8; 4 lanes per row)
        float mxA = -1e30f, mxB = -1e30f;
#pragma unroll
        for (int j = 0; j < 16; j++) {
            mxA = fmaxf(mxA, fmaxf(Sf[j][0], Sf[j][1]));
            mxB = fmaxf(mxB, fmaxf(Sf[j][2], Sf[j][3]));
        }
        mxA = fmaxf(mxA, __shfl_xor_sync(0xffffffffu, mxA, 1));
        mxA = fmaxf(mxA, __shfl_xor_sync(0xffffffffu, mxA, 2));
        mxB = fmaxf(mxB, __shfl_xor_sync(0xffffffffu, mxB, 1));
        mxB = fmaxf(mxB, __shfl_xor_sync(0xffffffffu, mxB, 2));
        float mnA = fmaxf(mA, mxA), mnB = fmaxf(mB, mxB);
        float cA = __expf(mA - mnA), cB = __expf(mB - mnB);
        mA = mnA; mB = mnB;
        float sA = 0.f, sB = 0.f;
#pragma unroll
        for (int j = 0; j < 16; j++) {
            Sf[j][0] = __expf(Sf[j][0] - mnA); sA += Sf[j][0];
            Sf[j][1] = __expf(Sf[j][1] - mnA); sA += Sf[j][1];
            Sf[j][2] = __expf(Sf[j][2] - mnB); sB += Sf[j][2];
            Sf[j][3] = __expf(Sf[j][3] - mnB); sB += Sf[j][3];
        }
        sA += __shfl_xor_sync(0xffffffffu, sA, 1);
        sA += __shfl_xor_sync(0xffffffffu, sA, 2);
        sB += __shfl_xor_sync(0xffffffffu, sB, 1);
        sB += __shfl_xor_sync(0xffffffffu, sB, 2);
        lA = lA * cA + sA;
        lB = lB * cB + sB;
#pragma unroll
        for (int j = 0; j < 8; j++) {
            Oa[j][0] *= cA; Oa[j][1] *= cA;
            Oa[j][2] *= cB; Oa[j][3] *= cB;
        }

        // O += P V  (P from S frags, split; V via ldmatrix.trans, split)
#pragma unroll
        for (int sc = 0; sc < 8; sc++) {
            uint32_t Ph[4], Pl[4];
            pack2(Sf[2*sc][0],   Sf[2*sc][1],   Ph[0], Pl[0]);
            pack2(Sf[2*sc][2],   Sf[2*sc][3],   Ph[1], Pl[1]);
            pack2(Sf[2*sc+1][0], Sf[2*sc+1][1], Ph[2], Pl[2]);
            pack2(Sf[2*sc+1][2], Sf[2*sc+1][3], Ph[3], Pl[3]);
#pragma unroll
            for (int dg = 0; dg < 4; dg++) {
                int row = sc * 16 + (lane & 15);
                int col = dg * 16 + ((lane >> 4) << 3);
                uint32_t vd = so + 2 * TB + (uint32_t)(row * LDA + col) * 2;
                uint32_t Vh4[4], Vl4[4];
                ldm_x4_t(Vh4, vd);
                ldm_x4_t(Vl4, vd + TB);
                mma_bf16(Oa[2*dg],   Ph, Vh4);
                mma_bf16(Oa[2*dg],   Ph, Vl4);
                mma_bf16(Oa[2*dg],   Pl, Vh4);
                mma_bf16(Oa[2*dg+1], Ph, Vh4 + 2);
                mma_bf16(Oa[2*dg+1], Ph, Vl4 + 2);
                mma_bf16(Oa[2*dg+1], Pl, Vh4 + 2);
            }
        }
        __syncthreads();   // stage reuse safety
    }

    // epilogue: O / l -> g_ctx [t,b,E]
    float iA = 1.f / lA, iB = 1.f / lB;
    int tA = t0 + w * 16 + (lane >> 2);
#pragma unroll
    for (int dj = 0; dj < 8; dj++) {
        int d = h * 64 + dj * 8 + ((lane & 3) << 1);
        float2 vA = {Oa[dj][0] * iA, Oa[dj][1] * iA};
        float2 vB = {Oa[dj][2] * iB, Oa[dj][3] * iB};
        *(float2*)&g_ctx[((size_t)tA * B_ + b) * E_ + d] = vA;
        *(float2*)&g_ctx[((size_t)(tA + 8) * B_ + b) * E_ + d] = vB;
    }
}

// ---------------------------------------------------------------------------
// kernel_launch
// ---------------------------------------------------------------------------
static float* s_qkv = nullptr;
static float* s_ctx = nullptr;
static __nv_bfloat16 *s_qh, *s_ql, *s_wih, *s_wil, *s_woh, *s_wol, *s_ch, *s_cl;
static __nv_bfloat16 *s_kvh, *s_kvl;
static bool s_init = false;
static const int GEMM_SMEM = 2 * 4 * 128 * 40 * 2;        // 81920
static const int ATTN_SMEM = 10 * 128 * 72 * 2;           // 184320

extern "C" void kernel_launch(void* const* d_in, const int* in_sizes, int n_in,
                              void* d_out, int out_size)
{
    const float* query = (const float*)d_in[0];
    const float* dist  = (const float*)d_in[1];
    const float* w_in  = (const float*)d_in[2];
    const float* b_in  = (const float*)d_in[3];
    const float* w_out = (const float*)d_in[4];
    const float* b_out = (const float*)d_in[5];
    float* out = (float*)d_out;

    if (!s_init) {
        cudaGetSymbolAddress((void**)&s_qkv, g_qkv);
        cudaGetSymbolAddress((void**)&s_ctx, g_ctx);
        cudaGetSymbolAddress((void**)&s_qh,  g_q_hi);  cudaGetSymbolAddress((void**)&s_ql,  g_q_lo);
        cudaGetSymbolAddress((void**)&s_wih, g_wi_hi); cudaGetSymbolAddress((void**)&s_wil, g_wi_lo);
        cudaGetSymbolAddress((void**)&s_woh, g_wo_hi); cudaGetSymbolAddress((void**)&s_wol, g_wo_lo);
        cudaGetSymbolAddress((void**)&s_ch,  g_c_hi);  cudaGetSymbolAddress((void**)&s_cl,  g_c_lo);
        cudaGetSymbolAddress((void**)&s_kvh, g_qkv_h); cudaGetSymbolAddress((void**)&s_kvl, g_qkv_l);
        cudaFuncSetAttribute(gemm_mma, cudaFuncAttributeMaxDynamicSharedMemorySize, GEMM_SMEM);
        cudaFuncSetAttribute(attn_mma, cudaFuncAttributeMaxDynamicSharedMemorySize, ATTN_SMEM);
        s_init = true;
    }

    // input splits
    split_bf16_kernel<<<(T_*B_*E_/4 + 255)/256, 256>>>(query, s_qh, s_ql, T_*B_*E_/4);
    split_bf16_kernel<<<(E3_*E_/4 + 255)/256, 256>>>(w_in, s_wih, s_wil, E3_*E_/4);
    split_bf16_kernel<<<(E_*E_/4 + 255)/256, 256>>>(w_out, s_woh, s_wol, E_*E_/4);

    // 1) QKV projection (HMMA)
    gemm_mma<<<dim3(32, 12), 256, GEMM_SMEM>>>(s_qh, s_ql, s_wih, s_wil, b_in, s_qkv, E3_);

    // 2) split qkv -> bf16 hi/lo, then HMMA flash attention with bias
    split_bf16_kernel<<<(T_*B_*E3_/4 + 255)/256, 256>>>(s_qkv, s_kvh, s_kvl, T_*B_*E3_/4);
    attn_mma<<<dim3(8, 32), 256, ATTN_SMEM>>>(dist);

    // 3) split ctx, output projection (HMMA)
    split_bf16_kernel<<<(T_*B_*E_/4 + 255)/256, 256>>>(s_ctx, s_ch, s_cl, T_*B_*E_/4);
    gemm_mma<<<dim3(32, 4), 256, GEMM_SMEM>>>(s_ch, s_cl, s_woh, s_wol, b_out, out, E_);
}